// round 2
// baseline (speedup 1.0000x reference)
#include <cuda_runtime.h>
#include <cuda_bf16.h>
#include <cstdint>

// Problem dims (fixed)
#define MM   16384      // BS*L
#define KK   1024       // H
#define NN   1024       // NH*HD
#define LSEQ 2048
#define BSZ  8
#define NHD  16         // NH
#define HDD  64         // HD

// ---------------- scratch (static device globals; no allocs allowed) --------
__device__ float         g_K1[(size_t)MM * NN];     // relu(X@K1_w + b)
__device__ float         g_V1[(size_t)MM * NN];     // relu(X@V1_w + b)
__device__ unsigned char g_valid[(size_t)MM * NHD]; // dots > 0.5
__device__ int           g_fa[BSZ * NHD * LSEQ];
__device__ int           g_fb[BSZ * NHD * LSEQ];
__device__ int           g_ba[BSZ * NHD * LSEQ];
__device__ int           g_bb[BSZ * NHD * LSEQ];

// ---------------- fp32 GEMM + bias + relu -----------------------------------
// C[M,N] = relu(A[M,K] @ B[K,N] + bias[N]); tiles 128x128x16, 256 thr, 8x8/thr
__global__ __launch_bounds__(256, 2)
void gemm_relu_kernel(const float* __restrict__ A, const float* __restrict__ B,
                      const float* __restrict__ bias, float* __restrict__ C)
{
    __shared__ float As[2][16][128];
    __shared__ float Bs[2][16][128];

    const int tid = threadIdx.x;
    const int tx  = tid & 15;   // 0..15  (N direction)
    const int ty  = tid >> 4;   // 0..15  (M direction)
    const int bm  = blockIdx.y * 128;
    const int bn  = blockIdx.x * 128;

    // A-tile load mapping: 128 rows x 16 cols = 512 float4; 2 per thread
    const int arow = tid >> 2;          // 0..63 (plus +64 second pass)
    const int acol = (tid & 3) * 4;     // 0,4,8,12
    // B-tile load mapping: 16 rows x 128 cols = 512 float4; 2 per thread
    const int brow = tid >> 5;          // 0..7  (plus +8 second pass)
    const int bcol = (tid & 31) * 4;    // 0..124

    const float* Aptr = A + (size_t)bm * KK;
    const float* Bptr = B + bn;

    float acc[8][8];
    #pragma unroll
    for (int i = 0; i < 8; i++)
        #pragma unroll
        for (int j = 0; j < 8; j++) acc[i][j] = 0.0f;

    // prologue: tile 0 -> buffer 0
    {
        #pragma unroll
        for (int p = 0; p < 2; p++) {
            int r = arow + p * 64;
            float4 v = *(const float4*)(Aptr + (size_t)r * KK + acol);
            As[0][acol + 0][r] = v.x;
            As[0][acol + 1][r] = v.y;
            As[0][acol + 2][r] = v.z;
            As[0][acol + 3][r] = v.w;
        }
        #pragma unroll
        for (int p = 0; p < 2; p++) {
            int r = brow + p * 8;
            float4 v = *(const float4*)(Bptr + (size_t)r * NN + bcol);
            *(float4*)&Bs[0][r][bcol] = v;
        }
    }
    __syncthreads();

    int buf = 0;
    for (int kt = 0; kt < KK / 16; kt++) {
        const int nbuf = buf ^ 1;
        if (kt < KK / 16 - 1) {
            const int koff = (kt + 1) * 16;
            #pragma unroll
            for (int p = 0; p < 2; p++) {
                int r = arow + p * 64;
                float4 v = *(const float4*)(Aptr + (size_t)r * KK + koff + acol);
                As[nbuf][acol + 0][r] = v.x;
                As[nbuf][acol + 1][r] = v.y;
                As[nbuf][acol + 2][r] = v.z;
                As[nbuf][acol + 3][r] = v.w;
            }
            #pragma unroll
            for (int p = 0; p < 2; p++) {
                int r = brow + p * 8;
                float4 v = *(const float4*)(Bptr + (size_t)(koff + r) * NN + bcol);
                *(float4*)&Bs[nbuf][r][bcol] = v;
            }
        }
        #pragma unroll
        for (int k = 0; k < 16; k++) {
            float ar[8], br[8];
            *(float4*)&ar[0] = *(const float4*)&As[buf][k][ty * 8];
            *(float4*)&ar[4] = *(const float4*)&As[buf][k][ty * 8 + 4];
            *(float4*)&br[0] = *(const float4*)&Bs[buf][k][tx * 8];
            *(float4*)&br[4] = *(const float4*)&Bs[buf][k][tx * 8 + 4];
            #pragma unroll
            for (int i = 0; i < 8; i++)
                #pragma unroll
                for (int j = 0; j < 8; j++)
                    acc[i][j] += ar[i] * br[j];
        }
        __syncthreads();
        buf = nbuf;
    }

    // epilogue: bias + relu + store
    float bv[8];
    #pragma unroll
    for (int j = 0; j < 8; j++) bv[j] = bias[bn + tx * 8 + j];

    #pragma unroll
    for (int i = 0; i < 8; i++) {
        const int row = bm + ty * 8 + i;
        float* Crow = C + (size_t)row * NN + bn + tx * 8;
        #pragma unroll
        for (int j = 0; j < 8; j++) {
            float v = acc[i][j] + bv[j];
            acc[i][j] = v > 0.0f ? v : 0.0f;
        }
        *(float4*)(Crow)     = *(float4*)&acc[i][0];
        *(float4*)(Crow + 4) = *(float4*)&acc[i][4];
    }
}

// ---------------- dots = sum_h relu(K1)[row, n*64+h]*RH[n,h]; valid = >0.5 ---
// grid = MM blocks, 512 threads (16 warps = 16 heads)
__global__ __launch_bounds__(512)
void dots_kernel(const float* __restrict__ RH)
{
    const int row  = blockIdx.x;
    const int head = threadIdx.x >> 5;
    const int lane = threadIdx.x & 31;
    const float* kp = g_K1 + (size_t)row * NN + head * HDD;
    const float* rp = RH + head * HDD;
    float s = kp[lane] * rp[lane] + kp[lane + 32] * rp[lane + 32];
    #pragma unroll
    for (int o = 16; o; o >>= 1) s += __shfl_xor_sync(0xffffffffu, s, o);
    if (lane == 0)
        g_valid[(size_t)row * NHD + head] = (s > 0.5f) ? 1 : 0;
}

// ---------------- nearest-valid scans (exact reference semantics) -----------
// grid = BSZ*NHD blocks. Thread 0 of each block runs the L-length serial scan.
__global__ __launch_bounds__(256)
void scan_kernel()
{
    const int b = blockIdx.x >> 4;
    const int n = blockIdx.x & 15;
    __shared__ unsigned char sv[LSEQ];
    for (int t = threadIdx.x; t < LSEQ; t += blockDim.x)
        sv[t] = g_valid[((size_t)b * LSEQ + t) * NHD + n];
    __syncthreads();
    if (threadIdx.x == 0) {
        const int base = (b * NHD + n) * LSEQ;
        // forward: positions 1..L-1 trigger; store (last, second-last) idx
        int a = 0, b2 = 0;
        g_fa[base] = 0; g_fb[base] = 0;
        for (int t = 1; t < LSEQ; t++) {
            if (sv[t]) { b2 = a; a = t; }
            g_fa[base + t] = a;
            g_fb[base + t] = b2;
        }
        // backward: positions L-2..0; stored value is (L-1 - j) per reference
        int aa = LSEQ - 1, ab = LSEQ - 1;
        g_ba[base + LSEQ - 1] = LSEQ - 1;
        g_bb[base + LSEQ - 1] = LSEQ - 1;
        for (int j = LSEQ - 2; j >= 0; j--) {
            if (sv[j]) { ab = aa; aa = (LSEQ - 1) - j; }
            g_ba[base + j] = aa;
            g_bb[base + j] = ab;
        }
    }
}

// ---------------- gather + weighted sum -------------------------------------
// one warp per (b, l, n); lane covers h and h+32
__global__ __launch_bounds__(256)
void gather_kernel(const float* __restrict__ bw, float* __restrict__ out)
{
    const int gw   = (int)((blockIdx.x * blockDim.x + threadIdx.x) >> 5);
    const int lane = threadIdx.x & 31;
    const int n = gw & 15;
    const int l = (gw >> 4) & (LSEQ - 1);
    const int b = gw >> 15;

    const int mbase = (b * NHD + n) * LSEQ + l;
    const int i0 = g_fa[mbase];
    const int i1 = g_fb[mbase];
    const int i2 = g_ba[mbase];
    const int i3 = g_bb[mbase];

    const float w0 = bw[n * 4 + 0];
    const float w1 = bw[n * 4 + 1];
    const float w2 = bw[n * 4 + 2];
    const float w3 = bw[n * 4 + 3];

    const size_t vbase = (size_t)b * LSEQ * NN + (size_t)n * HDD + lane;
    const float* V = g_V1;

    float o0 = w0 * V[vbase + (size_t)i0 * NN] + w1 * V[vbase + (size_t)i1 * NN]
             + w2 * V[vbase + (size_t)i2 * NN] + w3 * V[vbase + (size_t)i3 * NN];
    const size_t vb2 = vbase + 32;
    float o1 = w0 * V[vb2 + (size_t)i0 * NN] + w1 * V[vb2 + (size_t)i1 * NN]
             + w2 * V[vb2 + (size_t)i2 * NN] + w3 * V[vb2 + (size_t)i3 * NN];

    const size_t obase = ((size_t)b * LSEQ + l) * NN + (size_t)n * HDD + lane;
    out[obase]      = o0;
    out[obase + 32] = o1;
}

// ---------------- launch ------------------------------------------------------
extern "C" void kernel_launch(void* const* d_in, const int* in_sizes, int n_in,
                              void* d_out, int out_size)
{
    (void)in_sizes; (void)n_in; (void)out_size;
    const float* hid  = (const float*)d_in[0];
    const float* K1w  = (const float*)d_in[1];
    const float* K1b  = (const float*)d_in[2];
    const float* V1w  = (const float*)d_in[3];
    const float* V1b  = (const float*)d_in[4];
    const float* bw   = (const float*)d_in[5];
    const float* RH   = (const float*)d_in[6];
    float* out = (float*)d_out;

    float* pK1 = nullptr;
    float* pV1 = nullptr;
    cudaGetSymbolAddress((void**)&pK1, g_K1);
    cudaGetSymbolAddress((void**)&pV1, g_V1);

    dim3 ggrid(NN / 128, MM / 128);   // (8, 128)
    gemm_relu_kernel<<<ggrid, 256>>>(hid, K1w, K1b, pK1);
    gemm_relu_kernel<<<ggrid, 256>>>(hid, V1w, V1b, pV1);

    dots_kernel<<<MM, 512>>>(RH);

    scan_kernel<<<BSZ * NHD, 256>>>();

    // one warp per (b,l,n): 8*2048*16 warps, 8 warps/block
    const int total_warps = BSZ * LSEQ * NHD;
    gather_kernel<<<total_warps / 8, 256>>>(bw, out);
}

// round 7
// speedup vs baseline: 1.2010x; 1.2010x over previous
#include <cuda_runtime.h>
#include <cstdint>

// Problem dims (fixed)
#define MM   16384      // BS*L
#define KK   1024       // H
#define NN   1024       // NH*HD
#define LSEQ 2048
#define BSZ  8
#define NHD  16         // NH
#define HDD  64         // HD

// GEMM tiling
#define TILE_M 128
#define TILE_N 128
#define KCH    16
#define NKT    (KK / KCH)          // 64 chunks
#define TPAD   20                  // padded row stride (floats) -> conflict-free
#define TILE_BYTES (128 * TPAD * 4)    // 10240
#define STAGE_BYTES (4 * TILE_BYTES)   // Ahi, Alo, Bhi, Blo
#define SMEM_TOTAL (2 * STAGE_BYTES)   // 81920

// ---------------- scratch (static device globals; no allocs allowed) --------
__device__ float         g_K1[(size_t)MM * NN];
__device__ float         g_V1[(size_t)MM * NN];
__device__ float         g_Ahi[(size_t)MM * KK];
__device__ float         g_Alo[(size_t)MM * KK];
__device__ float         g_WtKhi[(size_t)KK * NN];   // W^T hi, [n][k]
__device__ float         g_WtKlo[(size_t)KK * NN];
__device__ float         g_WtVhi[(size_t)KK * NN];
__device__ float         g_WtVlo[(size_t)KK * NN];
__device__ unsigned char g_valid[(size_t)MM * NHD];
__device__ int           g_fa[BSZ * NHD * LSEQ];
__device__ int           g_fb[BSZ * NHD * LSEQ];
__device__ int           g_ba[BSZ * NHD * LSEQ];
__device__ int           g_bb[BSZ * NHD * LSEQ];

// ---------------- PTX helpers ------------------------------------------------
__device__ __forceinline__ uint32_t s2u(const void* p) {
    uint32_t a;
    asm("{ .reg .u64 t; cvta.to.shared.u64 t, %1; cvt.u32.u64 %0, t; }"
        : "=r"(a) : "l"(p));
    return a;
}

__device__ __forceinline__ float tf32r(float x) {
    uint32_t u;
    asm("cvt.rna.tf32.f32 %0, %1;" : "=r"(u) : "f"(x));
    return __uint_as_float(u);
}

#define CP16(dst, src) \
    asm volatile("cp.async.cg.shared.global [%0], [%1], 16;\n" :: "r"(dst), "l"(src))
#define CP_COMMIT()  asm volatile("cp.async.commit_group;")
#define CP_WAIT(n)   asm volatile("cp.async.wait_group %0;" :: "n"(n))

// m16n8k8 tf32 MMA: D = A*B + D (fp32 accum in registers)
#define MMA_TF32(c, a0, a1, a2, a3, b0, b1) \
    asm volatile( \
        "mma.sync.aligned.m16n8k8.row.col.f32.tf32.tf32.f32 " \
        "{%0,%1,%2,%3}, {%4,%5,%6,%7}, {%8,%9}, {%0,%1,%2,%3};" \
        : "+f"((c)[0]), "+f"((c)[1]), "+f"((c)[2]), "+f"((c)[3]) \
        : "r"(__float_as_uint(a0)), "r"(__float_as_uint(a1)), \
          "r"(__float_as_uint(a2)), "r"(__float_as_uint(a3)), \
          "r"(__float_as_uint(b0)), "r"(__float_as_uint(b1)))

// ---------------- prep: tf32 split of A (hidden states) ----------------------
__global__ __launch_bounds__(256)
void asplit_kernel(const float* __restrict__ X)
{
    const size_t n4 = (size_t)MM * KK / 4;
    const float4* x4 = (const float4*)X;
    float4* h4 = (float4*)g_Ahi;
    float4* l4 = (float4*)g_Alo;
    for (size_t i = (size_t)blockIdx.x * blockDim.x + threadIdx.x; i < n4;
         i += (size_t)gridDim.x * blockDim.x) {
        float4 v = x4[i], h, l;
        h.x = tf32r(v.x); l.x = tf32r(v.x - h.x);
        h.y = tf32r(v.y); l.y = tf32r(v.y - h.y);
        h.z = tf32r(v.z); l.z = tf32r(v.z - h.z);
        h.w = tf32r(v.w); l.w = tf32r(v.w - h.w);
        h4[i] = h; l4[i] = l;
    }
}

// ---------------- prep: transpose + tf32 split of both weight matrices -------
__global__ __launch_bounds__(256)
void wsplit_kernel(const float* __restrict__ WK, const float* __restrict__ WV)
{
    __shared__ float t[32][33];
    const float* W  = blockIdx.z ? WV : WK;
    float* Oh = blockIdx.z ? g_WtVhi : g_WtKhi;
    float* Ol = blockIdx.z ? g_WtVlo : g_WtKlo;
    const int n0 = blockIdx.x * 32, k0 = blockIdx.y * 32;
    const int tx = threadIdx.x, ty = threadIdx.y;
    #pragma unroll
    for (int j = 0; j < 32; j += 8)
        t[ty + j][tx] = W[(size_t)(k0 + ty + j) * NN + n0 + tx];
    __syncthreads();
    #pragma unroll
    for (int j = 0; j < 32; j += 8) {
        float v = t[tx][ty + j];                 // W[k0+tx][n0+ty+j]
        float h = tf32r(v), l = tf32r(v - h);
        size_t o = (size_t)(n0 + ty + j) * KK + k0 + tx;
        Oh[o] = h; Ol[o] = l;
    }
}

// ---------------- mma.sync 3xTF32 GEMM: C = relu(A@W + bias) -----------------
// grid (8, 128): x = N tile, y = M tile. 256 threads = 8 warps (2 x 4),
// warp tile 64x32, per-warp 4 mtiles x 4 ntiles of m16n8k8.
__global__ __launch_bounds__(256, 2)
void gemm_mma_tf32x3_kernel(const float* __restrict__ Ahi, const float* __restrict__ Alo,
                            const float* __restrict__ Bhi, const float* __restrict__ Blo,
                            const float* __restrict__ bias, float* __restrict__ C)
{
    extern __shared__ float smem[];
    const uint32_t sb = s2u(smem);
    const int tid  = threadIdx.x;
    const int wid  = tid >> 5;
    const int lane = tid & 31;
    const int wm   = wid >> 2;           // 0..1  (64-row slab)
    const int wn   = wid & 3;            // 0..3  (32-col slab)
    const int g    = lane >> 2;          // groupID
    const int t    = lane & 3;           // threadID_in_group
    const int bm   = blockIdx.y;
    const int bn   = blockIdx.x;

    const float* Ag[2] = { Ahi + (size_t)bm * TILE_M * KK,
                           Alo + (size_t)bm * TILE_M * KK };
    const float* Bg[2] = { Bhi + (size_t)bn * TILE_N * KK,
                           Blo + (size_t)bn * TILE_N * KK };

    // loader: 4 tiles (Ahi, Alo, Bhi, Blo), each 128 rows x 16 floats
    auto load_chunk = [&](int kt, int s) {
        const uint32_t stage = sb + (uint32_t)s * STAGE_BYTES;
        const int k0 = kt * KCH;
        #pragma unroll
        for (int tile = 0; tile < 4; tile++) {
            const float* src = (tile < 2) ? Ag[tile] : Bg[tile - 2];
            const uint32_t dst = stage + (uint32_t)tile * TILE_BYTES;
            #pragma unroll
            for (int i = 0; i < 2; i++) {
                int idx = i * 256 + tid;          // 0..511
                int r = idx >> 2, c = idx & 3;
                CP16(dst + (uint32_t)(r * (TPAD * 4) + c * 16),
                     src + (size_t)r * KK + k0 + c * 4);
            }
        }
        CP_COMMIT();
    };

    float acc[4][4][4];
    #pragma unroll
    for (int mt = 0; mt < 4; mt++)
        #pragma unroll
        for (int nt = 0; nt < 4; nt++)
            #pragma unroll
            for (int i = 0; i < 4; i++) acc[mt][nt][i] = 0.0f;

    load_chunk(0, 0);

    for (int kt = 0; kt < NKT; kt++) {
        const int s = kt & 1;
        if (kt + 1 < NKT) { load_chunk(kt + 1, s ^ 1); CP_WAIT(1); }
        else             { CP_WAIT(0); }
        __syncthreads();

        const float* Ah = smem + (size_t)s * (STAGE_BYTES / 4);
        const float* Al = Ah + TILE_BYTES / 4;
        const float* Bh = Al + TILE_BYTES / 4;
        const float* Bl = Bh + TILE_BYTES / 4;

        #pragma unroll
        for (int k8 = 0; k8 < KCH; k8 += 8) {
            float bh[4][2], bl[4][2];
            #pragma unroll
            for (int nt = 0; nt < 4; nt++) {
                const int br = (wn * 32 + nt * 8 + g) * TPAD + k8 + t;
                bh[nt][0] = Bh[br];     bh[nt][1] = Bh[br + 4];
                bl[nt][0] = Bl[br];     bl[nt][1] = Bl[br + 4];
            }
            #pragma unroll
            for (int mt = 0; mt < 4; mt++) {
                const int ar = (wm * 64 + mt * 16 + g) * TPAD + k8 + t;
                const int ar8 = ar + 8 * TPAD;
                float ah0 = Ah[ar],  ah1 = Ah[ar8];
                float ah2 = Ah[ar + 4], ah3 = Ah[ar8 + 4];
                float al0 = Al[ar],  al1 = Al[ar8];
                float al2 = Al[ar + 4], al3 = Al[ar8 + 4];
                #pragma unroll
                for (int nt = 0; nt < 4; nt++) {
                    MMA_TF32(acc[mt][nt], ah0, ah1, ah2, ah3, bh[nt][0], bh[nt][1]);
                    MMA_TF32(acc[mt][nt], ah0, ah1, ah2, ah3, bl[nt][0], bl[nt][1]);
                    MMA_TF32(acc[mt][nt], al0, al1, al2, al3, bh[nt][0], bh[nt][1]);
                }
            }
        }
        __syncthreads();
    }

    // epilogue: bias + relu, direct global store (float2 per fragment row)
    #pragma unroll
    for (int nt = 0; nt < 4; nt++) {
        const int col0 = bn * TILE_N + wn * 32 + nt * 8 + 2 * t;
        const float b0 = bias[col0], b1 = bias[col0 + 1];
        #pragma unroll
        for (int mt = 0; mt < 4; mt++) {
            const int row0 = bm * TILE_M + wm * 64 + mt * 16 + g;
            float v0 = fmaxf(acc[mt][nt][0] + b0, 0.0f);
            float v1 = fmaxf(acc[mt][nt][1] + b1, 0.0f);
            float v2 = fmaxf(acc[mt][nt][2] + b0, 0.0f);
            float v3 = fmaxf(acc[mt][nt][3] + b1, 0.0f);
            *(float2*)(C + (size_t)row0 * NN + col0)       = make_float2(v0, v1);
            *(float2*)(C + (size_t)(row0 + 8) * NN + col0) = make_float2(v2, v3);
        }
    }
}

// ---------------- dots = sum_h relu(K1)[row, n*64+h]*RH[n,h]; valid = >0.5 ---
__global__ __launch_bounds__(512)
void dots_kernel(const float* __restrict__ RH)
{
    const int row  = blockIdx.x;
    const int head = threadIdx.x >> 5;
    const int lane = threadIdx.x & 31;
    const float* kp = g_K1 + (size_t)row * NN + head * HDD;
    const float* rp = RH + head * HDD;
    float s = kp[lane] * rp[lane] + kp[lane + 32] * rp[lane + 32];
    #pragma unroll
    for (int o = 16; o; o >>= 1) s += __shfl_xor_sync(0xffffffffu, s, o);
    if (lane == 0)
        g_valid[(size_t)row * NHD + head] = (s > 0.5f) ? 1 : 0;
}

// ---------------- nearest-valid scans (exact reference semantics) -----------
__global__ __launch_bounds__(256)
void scan_kernel()
{
    const int b = blockIdx.x >> 4;
    const int n = blockIdx.x & 15;
    __shared__ unsigned char sv[LSEQ];
    for (int t = threadIdx.x; t < LSEQ; t += blockDim.x)
        sv[t] = g_valid[((size_t)b * LSEQ + t) * NHD + n];
    __syncthreads();
    const int base = (b * NHD + n) * LSEQ;
    if (threadIdx.x == 0) {
        int a = 0, b2 = 0;
        g_fa[base] = 0; g_fb[base] = 0;
        for (int t = 1; t < LSEQ; t++) {
            if (sv[t]) { b2 = a; a = t; }
            g_fa[base + t] = a;
            g_fb[base + t] = b2;
        }
    } else if (threadIdx.x == 32) {
        int aa = LSEQ - 1, ab = LSEQ - 1;
        g_ba[base + LSEQ - 1] = LSEQ - 1;
        g_bb[base + LSEQ - 1] = LSEQ - 1;
        for (int j = LSEQ - 2; j >= 0; j--) {
            if (sv[j]) { ab = aa; aa = (LSEQ - 1) - j; }
            g_ba[base + j] = aa;
            g_bb[base + j] = ab;
        }
    }
}

// ---------------- gather + weighted sum -------------------------------------
__global__ __launch_bounds__(256)
void gather_kernel(const float* __restrict__ bw, float* __restrict__ out)
{
    const int gw   = (int)((blockIdx.x * blockDim.x + threadIdx.x) >> 5);
    const int lane = threadIdx.x & 31;
    const int n = gw & 15;
    const int l = (gw >> 4) & (LSEQ - 1);
    const int b = gw >> 15;

    const int mbase = (b * NHD + n) * LSEQ + l;
    const int i0 = g_fa[mbase];
    const int i1 = g_fb[mbase];
    const int i2 = g_ba[mbase];
    const int i3 = g_bb[mbase];

    const float w0 = bw[n * 4 + 0];
    const float w1 = bw[n * 4 + 1];
    const float w2 = bw[n * 4 + 2];
    const float w3 = bw[n * 4 + 3];

    const size_t vbase = (size_t)b * LSEQ * NN + (size_t)n * HDD + lane;
    const float* V = g_V1;

    float o0 = w0 * V[vbase + (size_t)i0 * NN] + w1 * V[vbase + (size_t)i1 * NN]
             + w2 * V[vbase + (size_t)i2 * NN] + w3 * V[vbase + (size_t)i3 * NN];
    const size_t vb2 = vbase + 32;
    float o1 = w0 * V[vb2 + (size_t)i0 * NN] + w1 * V[vb2 + (size_t)i1 * NN]
             + w2 * V[vb2 + (size_t)i2 * NN] + w3 * V[vb2 + (size_t)i3 * NN];

    const size_t obase = ((size_t)b * LSEQ + l) * NN + (size_t)n * HDD + lane;
    out[obase]      = o0;
    out[obase + 32] = o1;
}

// ---------------- launch ------------------------------------------------------
extern "C" void kernel_launch(void* const* d_in, const int* in_sizes, int n_in,
                              void* d_out, int out_size)
{
    (void)in_sizes; (void)n_in; (void)out_size;
    const float* hid  = (const float*)d_in[0];
    const float* K1w  = (const float*)d_in[1];
    const float* K1b  = (const float*)d_in[2];
    const float* V1w  = (const float*)d_in[3];
    const float* V1b  = (const float*)d_in[4];
    const float* bw   = (const float*)d_in[5];
    const float* RH   = (const float*)d_in[6];
    float* out = (float*)d_out;

    float *pK1, *pV1, *pAhi, *pAlo, *pWKh, *pWKl, *pWVh, *pWVl;
    cudaGetSymbolAddress((void**)&pK1,  g_K1);
    cudaGetSymbolAddress((void**)&pV1,  g_V1);
    cudaGetSymbolAddress((void**)&pAhi, g_Ahi);
    cudaGetSymbolAddress((void**)&pAlo, g_Alo);
    cudaGetSymbolAddress((void**)&pWKh, g_WtKhi);
    cudaGetSymbolAddress((void**)&pWKl, g_WtKlo);
    cudaGetSymbolAddress((void**)&pWVh, g_WtVhi);
    cudaGetSymbolAddress((void**)&pWVl, g_WtVlo);

    cudaFuncSetAttribute(gemm_mma_tf32x3_kernel,
                         cudaFuncAttributeMaxDynamicSharedMemorySize, SMEM_TOTAL);

    asplit_kernel<<<1024, 256>>>(hid);
    wsplit_kernel<<<dim3(32, 32, 2), dim3(32, 8)>>>(K1w, V1w);

    dim3 ggrid(NN / TILE_N, MM / TILE_M);   // (8, 128)
    gemm_mma_tf32x3_kernel<<<ggrid, 256, SMEM_TOTAL>>>(pAhi, pAlo, pWKh, pWKl, K1b, pK1);
    gemm_mma_tf32x3_kernel<<<ggrid, 256, SMEM_TOTAL>>>(pAhi, pAlo, pWVh, pWVl, V1b, pV1);

    dots_kernel<<<MM, 512>>>(RH);
    scan_kernel<<<BSZ * NHD, 256>>>();

    const int total_warps = BSZ * LSEQ * NHD;
    gather_kernel<<<total_warps / 8, 256>>>(bw, out);
}

// round 11
// speedup vs baseline: 2.4536x; 2.0430x over previous
#include <cuda_runtime.h>
#include <cuda_bf16.h>
#include <cstdint>

// Problem dims (fixed)
#define MM   16384      // BS*L
#define KK   1024       // H
#define NN   1024       // NH*HD
#define LSEQ 2048
#define BSZ  8
#define NHD  16         // NH
#define HDD  64         // HD

// ---- K GEMM (1xTF32) tiling ----
#define KKCH    32
#define KNKT    (KK / KKCH)              // 32
#define KPITCH  36                       // floats per row (32 used) - conflict free
#define KTILE_B (128 * KPITCH * 4)       // 18432
#define KSTAGE  (2 * KTILE_B)            // A, B
#define KSMEM   (2 * KSTAGE)             // 73728

// ---- V GEMM (bf16x3) tiling ----
#define VKCH    32                       // k per chunk (16 u32 pairs)
#define VNKT    (KK / VKCH)              // 32
#define VPITCH  20                       // u32 per row (16 used) - conflict free
#define VTILE_B (128 * VPITCH * 4)       // 10240
#define VSTAGE  (4 * VTILE_B)            // A1, A2, B1, B2
#define VSMEM   (2 * VSTAGE)             // 81920

#define EPS  0.005f
#define FCAP 32768

// ---------------- scratch (static device globals; no allocs allowed) --------
__device__ float         g_V1[(size_t)MM * NN];
__device__ float         g_Ahi[(size_t)MM * KK];        // tf32(X)
__device__ float         g_WtKhi[(size_t)KK * NN];      // tf32(K1_w^T) [n][k]
__device__ uint32_t      g_Ab1[(size_t)MM * KK / 2];    // bf16 pairs of X
__device__ uint32_t      g_Ab2[(size_t)MM * KK / 2];    // residual pairs
__device__ uint32_t      g_Wb1[(size_t)KK * NN / 2];    // bf16 pairs of V1_w^T [n][k/2]
__device__ uint32_t      g_Wb2[(size_t)KK * NN / 2];
__device__ unsigned char g_valid[(size_t)MM * NHD];
__device__ int           g_fa[BSZ * NHD * LSEQ];
__device__ int           g_fb[BSZ * NHD * LSEQ];
__device__ int           g_ba[BSZ * NHD * LSEQ];
__device__ int           g_bb[BSZ * NHD * LSEQ];
__device__ int           g_nflag;
__device__ int           g_flags[FCAP];

// ---------------- PTX helpers ------------------------------------------------
__device__ __forceinline__ uint32_t s2u(const void* p) {
    uint32_t a;
    asm("{ .reg .u64 t; cvta.to.shared.u64 t, %1; cvt.u32.u64 %0, t; }"
        : "=r"(a) : "l"(p));
    return a;
}

__device__ __forceinline__ float tf32r(float x) {
    uint32_t u;
    asm("cvt.rna.tf32.f32 %0, %1;" : "=r"(u) : "f"(x));
    return __uint_as_float(u);
}

__device__ __forceinline__ uint32_t bfpack(float a, float b) {
    __nv_bfloat162 t = __floats2bfloat162_rn(a, b);
    return *reinterpret_cast<uint32_t*>(&t);
}
__device__ __forceinline__ float bflo(uint32_t u) {
    __nv_bfloat162 t = *reinterpret_cast<__nv_bfloat162*>(&u);
    return __bfloat162float(t.x);
}
__device__ __forceinline__ float bfhi(uint32_t u) {
    __nv_bfloat162 t = *reinterpret_cast<__nv_bfloat162*>(&u);
    return __bfloat162float(t.y);
}

#define CP16(dst, src) \
    asm volatile("cp.async.cg.shared.global [%0], [%1], 16;\n" :: "r"(dst), "l"(src))
#define CP_COMMIT()  asm volatile("cp.async.commit_group;")
#define CP_WAIT(n)   asm volatile("cp.async.wait_group %0;" :: "n"(n))

// m16n8k8 tf32 MMA
#define MMA_TF32(c, a0, a1, a2, a3, b0, b1) \
    asm volatile( \
        "mma.sync.aligned.m16n8k8.row.col.f32.tf32.tf32.f32 " \
        "{%0,%1,%2,%3}, {%4,%5,%6,%7}, {%8,%9}, {%0,%1,%2,%3};" \
        : "+f"((c)[0]), "+f"((c)[1]), "+f"((c)[2]), "+f"((c)[3]) \
        : "r"(__float_as_uint(a0)), "r"(__float_as_uint(a1)), \
          "r"(__float_as_uint(a2)), "r"(__float_as_uint(a3)), \
          "r"(__float_as_uint(b0)), "r"(__float_as_uint(b1)))

// m16n8k16 bf16 MMA (operands are u32 bf16-pairs)
#define MMA_BF16(c, a0, a1, a2, a3, b0, b1) \
    asm volatile( \
        "mma.sync.aligned.m16n8k16.row.col.f32.bf16.bf16.f32 " \
        "{%0,%1,%2,%3}, {%4,%5,%6,%7}, {%8,%9}, {%0,%1,%2,%3};" \
        : "+f"((c)[0]), "+f"((c)[1]), "+f"((c)[2]), "+f"((c)[3]) \
        : "r"(a0), "r"(a1), "r"(a2), "r"(a3), "r"(b0), "r"(b1))

// ---------------- prep: splits of A (tf32 hi + bf16 pair x2) -----------------
__global__ __launch_bounds__(256)
void asplit_kernel(const float* __restrict__ X)
{
    if (blockIdx.x == 0 && threadIdx.x == 0) g_nflag = 0;
    const size_t n4 = (size_t)MM * KK / 4;
    const float4* x4 = (const float4*)X;
    float4* h4 = (float4*)g_Ahi;
    uint2* b14 = (uint2*)g_Ab1;
    uint2* b24 = (uint2*)g_Ab2;
    for (size_t i = (size_t)blockIdx.x * blockDim.x + threadIdx.x; i < n4;
         i += (size_t)gridDim.x * blockDim.x) {
        float4 v = x4[i], h;
        h.x = tf32r(v.x); h.y = tf32r(v.y);
        h.z = tf32r(v.z); h.w = tf32r(v.w);
        h4[i] = h;
        uint32_t p1 = bfpack(v.x, v.y);
        uint32_t p2 = bfpack(v.z, v.w);
        uint32_t r1 = bfpack(v.x - bflo(p1), v.y - bfhi(p1));
        uint32_t r2 = bfpack(v.z - bflo(p2), v.w - bfhi(p2));
        b14[i] = make_uint2(p1, p2);
        b24[i] = make_uint2(r1, r2);
    }
}

// ---------------- prep: weight transpose + split -----------------------------
// z=0: K weights -> tf32 [n][k]; z=1: V weights -> bf16 pairs x2 [n][k/2]
__global__ __launch_bounds__(256)
void wsplit_kernel(const float* __restrict__ WK, const float* __restrict__ WV)
{
    __shared__ float t[32][33];
    const int z = blockIdx.z;
    const float* W = z ? WV : WK;
    const int n0 = blockIdx.x * 32, k0 = blockIdx.y * 32;
    const int tx = threadIdx.x, ty = threadIdx.y;
    #pragma unroll
    for (int j = 0; j < 32; j += 8)
        t[ty + j][tx] = W[(size_t)(k0 + ty + j) * NN + n0 + tx];
    __syncthreads();
    if (z == 0) {
        #pragma unroll
        for (int j = 0; j < 32; j += 8) {
            float v = t[tx][ty + j];                 // W[k0+tx][n0+ty+j]
            g_WtKhi[(size_t)(n0 + ty + j) * KK + k0 + tx] = tf32r(v);
        }
    } else {
        const int tid = ty * 32 + tx;
        const int nl  = tid & 31;
        const int kp2 = tid >> 5;                    // 0..7
        #pragma unroll
        for (int jj = 0; jj < 2; jj++) {
            int kp = kp2 * 2 + jj;                   // 0..15
            float v0 = t[2 * kp][nl];
            float v1 = t[2 * kp + 1][nl];
            uint32_t u1 = bfpack(v0, v1);
            uint32_t u2 = bfpack(v0 - bflo(u1), v1 - bfhi(u1));
            size_t o = (size_t)(n0 + nl) * (KK / 2) + (k0 >> 1) + kp;
            g_Wb1[o] = u1;
            g_Wb2[o] = u2;
        }
    }
}

// ---------------- K GEMM: 1xTF32, fused dots+valid+flag epilogue -------------
// grid (8, 128): bn covers heads 2bn, 2bn+1 completely. 256 thr = 8 warps.
extern __shared__ char smem_raw[];
__global__ __launch_bounds__(256, 2)
void gemmK_kernel(const float* __restrict__ Ahi, const float* __restrict__ Bhi,
                  const float* __restrict__ bias, const float* __restrict__ RH)
{
    float* smem = (float*)smem_raw;
    __shared__ float sdots[128][4];
    const uint32_t sb = s2u(smem);
    const int tid  = threadIdx.x;
    const int wid  = tid >> 5;
    const int lane = tid & 31;
    const int wm   = wid >> 2;           // 0..1
    const int wn   = wid & 3;            // 0..3
    const int g    = lane >> 2;
    const int t    = lane & 3;
    const int bm   = blockIdx.y;
    const int bn   = blockIdx.x;

    const float* Ag = Ahi + (size_t)bm * 128 * KK;
    const float* Bg = Bhi + (size_t)bn * 128 * KK;

    auto load_chunk = [&](int kt, int s) {
        const uint32_t stage = sb + (uint32_t)s * KSTAGE;
        const int k0 = kt * KKCH;
        #pragma unroll
        for (int tile = 0; tile < 2; tile++) {
            const float* src = tile ? Bg : Ag;
            const uint32_t dst = stage + (uint32_t)tile * KTILE_B;
            #pragma unroll
            for (int i = 0; i < 4; i++) {
                int idx = i * 256 + tid;             // 0..1023
                int r = idx >> 3, c = idx & 7;
                CP16(dst + (uint32_t)(r * (KPITCH * 4) + c * 16),
                     src + (size_t)r * KK + k0 + c * 4);
            }
        }
        CP_COMMIT();
    };

    float acc[4][4][4];
    #pragma unroll
    for (int mt = 0; mt < 4; mt++)
        #pragma unroll
        for (int nt = 0; nt < 4; nt++)
            #pragma unroll
            for (int i = 0; i < 4; i++) acc[mt][nt][i] = 0.0f;

    load_chunk(0, 0);

    for (int kt = 0; kt < KNKT; kt++) {
        const int s = kt & 1;
        if (kt + 1 < KNKT) { load_chunk(kt + 1, s ^ 1); CP_WAIT(1); }
        else               { CP_WAIT(0); }
        __syncthreads();

        const float* Ah = smem + (size_t)s * (KSTAGE / 4);
        const float* Bh = Ah + KTILE_B / 4;

        #pragma unroll
        for (int k8 = 0; k8 < KKCH; k8 += 8) {
            float bf[4][2];
            #pragma unroll
            for (int nt = 0; nt < 4; nt++) {
                const int br = (wn * 32 + nt * 8 + g) * KPITCH + k8 + t;
                bf[nt][0] = Bh[br];
                bf[nt][1] = Bh[br + 4];
            }
            #pragma unroll
            for (int mt = 0; mt < 4; mt++) {
                const int ar  = (wm * 64 + mt * 16 + g) * KPITCH + k8 + t;
                const int ar8 = ar + 8 * KPITCH;
                float a0 = Ah[ar],     a1 = Ah[ar8];
                float a2 = Ah[ar + 4], a3 = Ah[ar8 + 4];
                #pragma unroll
                for (int nt = 0; nt < 4; nt++)
                    MMA_TF32(acc[mt][nt], a0, a1, a2, a3, bf[nt][0], bf[nt][1]);
            }
        }
        __syncthreads();
    }

    // ---- fused dots epilogue: per-thread relu(acc+bias)*RH partials --------
    float bv[4][2], rv[4][2];
    #pragma unroll
    for (int nt = 0; nt < 4; nt++) {
        const int lc = wn * 32 + nt * 8 + 2 * t;
        bv[nt][0] = bias[bn * 128 + lc];
        bv[nt][1] = bias[bn * 128 + lc + 1];
        rv[nt][0] = RH[bn * 128 + lc];
        rv[nt][1] = RH[bn * 128 + lc + 1];
    }
    #pragma unroll
    for (int mt = 0; mt < 4; mt++) {
        float p0 = 0.0f, p1 = 0.0f;
        #pragma unroll
        for (int nt = 0; nt < 4; nt++) {
            p0 += fmaxf(acc[mt][nt][0] + bv[nt][0], 0.0f) * rv[nt][0]
                + fmaxf(acc[mt][nt][1] + bv[nt][1], 0.0f) * rv[nt][1];
            p1 += fmaxf(acc[mt][nt][2] + bv[nt][0], 0.0f) * rv[nt][0]
                + fmaxf(acc[mt][nt][3] + bv[nt][1], 0.0f) * rv[nt][1];
        }
        p0 += __shfl_xor_sync(0xffffffffu, p0, 1);
        p0 += __shfl_xor_sync(0xffffffffu, p0, 2);
        p1 += __shfl_xor_sync(0xffffffffu, p1, 1);
        p1 += __shfl_xor_sync(0xffffffffu, p1, 2);
        if (t == 0) {
            sdots[wm * 64 + mt * 16 + g][wn]     = p0;
            sdots[wm * 64 + mt * 16 + g + 8][wn] = p1;
        }
    }
    __syncthreads();

    {
        const int row = tid >> 1;
        const int hl  = tid & 1;
        const float dot = sdots[row][2 * hl] + sdots[row][2 * hl + 1];
        const int grow = bm * 128 + row;
        const int head = bn * 2 + hl;
        g_valid[(size_t)grow * NHD + head] = (dot > 0.5f) ? 1 : 0;
        if (fabsf(dot - 0.5f) < EPS) {
            int slot = atomicAdd(&g_nflag, 1);
            if (slot < FCAP) g_flags[slot] = grow * NHD + head;
        }
    }
}

// ---------------- exact fp32 refinement of flagged dots ----------------------
__global__ __launch_bounds__(256)
void refine_kernel(const float* __restrict__ X, const float* __restrict__ W,
                   const float* __restrict__ RH)
{
    __shared__ float sred[64][5];
    __shared__ float s2[2];
    int cnt = g_nflag;
    if (cnt > FCAP) cnt = FCAP;
    const int tid = threadIdx.x;
    const int c   = tid & 63;
    const int seg = tid >> 6;

    for (int i = blockIdx.x; i < cnt; i += gridDim.x) {
        const int f    = g_flags[i];
        const int row  = f >> 4;
        const int head = f & 15;
        const float* x = X + (size_t)row * KK + seg * 256;
        const float* w = W + (size_t)(seg * 256) * NN + head * HDD + c;
        float p = 0.0f;
        #pragma unroll 8
        for (int k = 0; k < 256; k++) p += x[k] * w[(size_t)k * NN];
        sred[c][seg] = p;
        __syncthreads();
        if (tid < 64) {
            float k1 = sred[tid][0] + sred[tid][1] + sred[tid][2] + sred[tid][3];
            float v = fmaxf(k1, 0.0f) * RH[head * HDD + tid];
            #pragma unroll
            for (int o = 16; o; o >>= 1) v += __shfl_xor_sync(0xffffffffu, v, o);
            if ((tid & 31) == 0) s2[tid >> 5] = v;
        }
        __syncthreads();
        if (tid == 0)
            g_valid[(size_t)row * NHD + head] = (s2[0] + s2[1] > 0.5f) ? 1 : 0;
        __syncthreads();
    }
}

// ---------------- V GEMM: bf16x3, relu+bias epilogue -------------------------
__global__ __launch_bounds__(256, 2)
void gemmV_kernel(const uint32_t* __restrict__ A1, const uint32_t* __restrict__ A2,
                  const uint32_t* __restrict__ B1, const uint32_t* __restrict__ B2,
                  const float* __restrict__ bias, float* __restrict__ C)
{
    uint32_t* smem = (uint32_t*)smem_raw;
    const uint32_t sb = s2u(smem);
    const int tid  = threadIdx.x;
    const int wid  = tid >> 5;
    const int lane = tid & 31;
    const int wm   = wid >> 2;
    const int wn   = wid & 3;
    const int g    = lane >> 2;
    const int t    = lane & 3;
    const int bm   = blockIdx.y;
    const int bn   = blockIdx.x;

    const uint32_t* src4[4] = {
        A1 + (size_t)bm * 128 * (KK / 2), A2 + (size_t)bm * 128 * (KK / 2),
        B1 + (size_t)bn * 128 * (KK / 2), B2 + (size_t)bn * 128 * (KK / 2) };

    auto load_chunk = [&](int kt, int s) {
        const uint32_t stage = sb + (uint32_t)s * VSTAGE;
        const int kp0 = kt * (VKCH / 2);             // u32 offset
        #pragma unroll
        for (int tile = 0; tile < 4; tile++) {
            const uint32_t* src = src4[tile];
            const uint32_t dst = stage + (uint32_t)tile * VTILE_B;
            #pragma unroll
            for (int i = 0; i < 2; i++) {
                int idx = i * 256 + tid;             // 0..511
                int r = idx >> 2, c = idx & 3;
                CP16(dst + (uint32_t)(r * (VPITCH * 4) + c * 16),
                     src + (size_t)r * (KK / 2) + kp0 + c * 4);
            }
        }
        CP_COMMIT();
    };

    float acc[4][4][4];
    #pragma unroll
    for (int mt = 0; mt < 4; mt++)
        #pragma unroll
        for (int nt = 0; nt < 4; nt++)
            #pragma unroll
            for (int i = 0; i < 4; i++) acc[mt][nt][i] = 0.0f;

    load_chunk(0, 0);

    for (int kt = 0; kt < VNKT; kt++) {
        const int s = kt & 1;
        if (kt + 1 < VNKT) { load_chunk(kt + 1, s ^ 1); CP_WAIT(1); }
        else               { CP_WAIT(0); }
        __syncthreads();

        const uint32_t* Sa1 = smem + (size_t)s * (VSTAGE / 4);
        const uint32_t* Sa2 = Sa1 + VTILE_B / 4;
        const uint32_t* Sb1 = Sa2 + VTILE_B / 4;
        const uint32_t* Sb2 = Sb1 + VTILE_B / 4;

        #pragma unroll
        for (int h = 0; h < 2; h++) {                // two k16 halves
            const int pb = h * 8;
            uint32_t b1[4][2], b2[4][2];
            #pragma unroll
            for (int nt = 0; nt < 4; nt++) {
                const int br = (wn * 32 + nt * 8 + g) * VPITCH + pb + t;
                b1[nt][0] = Sb1[br]; b1[nt][1] = Sb1[br + 4];
                b2[nt][0] = Sb2[br]; b2[nt][1] = Sb2[br + 4];
            }
            #pragma unroll
            for (int mt = 0; mt < 4; mt++) {
                const int ar  = (wm * 64 + mt * 16 + g) * VPITCH + pb + t;
                const int ar8 = ar + 8 * VPITCH;
                uint32_t a10 = Sa1[ar],     a11 = Sa1[ar8];
                uint32_t a12 = Sa1[ar + 4], a13 = Sa1[ar8 + 4];
                uint32_t a20 = Sa2[ar],     a21 = Sa2[ar8];
                uint32_t a22 = Sa2[ar + 4], a23 = Sa2[ar8 + 4];
                #pragma unroll
                for (int nt = 0; nt < 4; nt++) {
                    MMA_BF16(acc[mt][nt], a10, a11, a12, a13, b1[nt][0], b1[nt][1]);
                    MMA_BF16(acc[mt][nt], a10, a11, a12, a13, b2[nt][0], b2[nt][1]);
                    MMA_BF16(acc[mt][nt], a20, a21, a22, a23, b1[nt][0], b1[nt][1]);
                }
            }
        }
        __syncthreads();
    }

    // epilogue: bias + relu, direct global store
    #pragma unroll
    for (int nt = 0; nt < 4; nt++) {
        const int col0 = bn * 128 + wn * 32 + nt * 8 + 2 * t;
        const float b0 = bias[col0], b1 = bias[col0 + 1];
        #pragma unroll
        for (int mt = 0; mt < 4; mt++) {
            const int row0 = bm * 128 + wm * 64 + mt * 16 + g;
            float v0 = fmaxf(acc[mt][nt][0] + b0, 0.0f);
            float v1 = fmaxf(acc[mt][nt][1] + b1, 0.0f);
            float v2 = fmaxf(acc[mt][nt][2] + b0, 0.0f);
            float v3 = fmaxf(acc[mt][nt][3] + b1, 0.0f);
            *(float2*)(C + (size_t)row0 * NN + col0)       = make_float2(v0, v1);
            *(float2*)(C + (size_t)(row0 + 8) * NN + col0) = make_float2(v2, v3);
        }
    }
}

// ---------------- nearest-valid scans (exact reference semantics) -----------
__global__ __launch_bounds__(256)
void scan_kernel()
{
    const int b = blockIdx.x >> 4;
    const int n = blockIdx.x & 15;
    __shared__ unsigned char sv[LSEQ];
    for (int t = threadIdx.x; t < LSEQ; t += blockDim.x)
        sv[t] = g_valid[((size_t)b * LSEQ + t) * NHD + n];
    __syncthreads();
    const int base = (b * NHD + n) * LSEQ;
    if (threadIdx.x == 0) {
        int a = 0, b2 = 0;
        g_fa[base] = 0; g_fb[base] = 0;
        for (int t = 1; t < LSEQ; t++) {
            if (sv[t]) { b2 = a; a = t; }
            g_fa[base + t] = a;
            g_fb[base + t] = b2;
        }
    } else if (threadIdx.x == 32) {
        int aa = LSEQ - 1, ab = LSEQ - 1;
        g_ba[base + LSEQ - 1] = LSEQ - 1;
        g_bb[base + LSEQ - 1] = LSEQ - 1;
        for (int j = LSEQ - 2; j >= 0; j--) {
            if (sv[j]) { ab = aa; aa = (LSEQ - 1) - j; }
            g_ba[base + j] = aa;
            g_bb[base + j] = ab;
        }
    }
}

// ---------------- gather + weighted sum -------------------------------------
__global__ __launch_bounds__(256)
void gather_kernel(const float* __restrict__ bw, float* __restrict__ out)
{
    const int gw   = (int)((blockIdx.x * blockDim.x + threadIdx.x) >> 5);
    const int lane = threadIdx.x & 31;
    const int n = gw & 15;
    const int l = (gw >> 4) & (LSEQ - 1);
    const int b = gw >> 15;

    const int mbase = (b * NHD + n) * LSEQ + l;
    const int i0 = g_fa[mbase];
    const int i1 = g_fb[mbase];
    const int i2 = g_ba[mbase];
    const int i3 = g_bb[mbase];

    const float w0 = bw[n * 4 + 0];
    const float w1 = bw[n * 4 + 1];
    const float w2 = bw[n * 4 + 2];
    const float w3 = bw[n * 4 + 3];

    const size_t vbase = (size_t)b * LSEQ * NN + (size_t)n * HDD + lane;
    const float* V = g_V1;

    float o0 = w0 * V[vbase + (size_t)i0 * NN] + w1 * V[vbase + (size_t)i1 * NN]
             + w2 * V[vbase + (size_t)i2 * NN] + w3 * V[vbase + (size_t)i3 * NN];
    const size_t vb2 = vbase + 32;
    float o1 = w0 * V[vb2 + (size_t)i0 * NN] + w1 * V[vb2 + (size_t)i1 * NN]
             + w2 * V[vb2 + (size_t)i2 * NN] + w3 * V[vb2 + (size_t)i3 * NN];

    const size_t obase = ((size_t)b * LSEQ + l) * NN + (size_t)n * HDD + lane;
    out[obase]      = o0;
    out[obase + 32] = o1;
}

// ---------------- launch ------------------------------------------------------
extern "C" void kernel_launch(void* const* d_in, const int* in_sizes, int n_in,
                              void* d_out, int out_size)
{
    (void)in_sizes; (void)n_in; (void)out_size;
    const float* hid  = (const float*)d_in[0];
    const float* K1w  = (const float*)d_in[1];
    const float* K1b  = (const float*)d_in[2];
    const float* V1w  = (const float*)d_in[3];
    const float* V1b  = (const float*)d_in[4];
    const float* bw   = (const float*)d_in[5];
    const float* RH   = (const float*)d_in[6];
    float* out = (float*)d_out;

    float *pV1, *pAhi, *pWKh;
    uint32_t *pAb1, *pAb2, *pWb1, *pWb2;
    cudaGetSymbolAddress((void**)&pV1,  g_V1);
    cudaGetSymbolAddress((void**)&pAhi, g_Ahi);
    cudaGetSymbolAddress((void**)&pWKh, g_WtKhi);
    cudaGetSymbolAddress((void**)&pAb1, g_Ab1);
    cudaGetSymbolAddress((void**)&pAb2, g_Ab2);
    cudaGetSymbolAddress((void**)&pWb1, g_Wb1);
    cudaGetSymbolAddress((void**)&pWb2, g_Wb2);

    cudaFuncSetAttribute(gemmK_kernel,
                         cudaFuncAttributeMaxDynamicSharedMemorySize, KSMEM);
    cudaFuncSetAttribute(gemmV_kernel,
                         cudaFuncAttributeMaxDynamicSharedMemorySize, VSMEM);

    asplit_kernel<<<1024, 256>>>(hid);
    wsplit_kernel<<<dim3(32, 32, 2), dim3(32, 8)>>>(K1w, V1w);

    dim3 ggrid(NN / 128, MM / 128);   // (8, 128)
    gemmK_kernel<<<ggrid, 256, KSMEM>>>(pAhi, pWKh, K1b, RH);
    gemmV_kernel<<<ggrid, 256, VSMEM>>>(pAb1, pAb2, pWb1, pWb2, V1b, pV1);

    refine_kernel<<<4096, 256>>>(hid, K1w, RH);
    scan_kernel<<<BSZ * NHD, 256>>>();

    const int total_warps = BSZ * LSEQ * NHD;
    gather_kernel<<<total_warps / 8, 256>>>(bw, out);
}